// round 1
// baseline (speedup 1.0000x reference)
#include <cuda_runtime.h>
#include <cuda_bf16.h>

// Problem constants
#define N_  10000
#define K_  32
#define M_  (N_ * K_)      // 320000
#define H_  128

// ---------------- scratch (device globals; no allocation allowed) -------------
__device__ float S_nh [N_ * H_];        // LN(node_features)
__device__ float S_c  [N_ * H_];        // center @ W_node_top   (reused: node FFN LN)
__device__ float S_nf1[N_ * H_];        // node residual after attention
__device__ float S_eh [M_ * H_];        // edge_hidden -> msg (in place)
__device__ float S_nh2[M_ * H_];        // node_hid     -> edge FFN LN (reused)
__device__ float S_big[M_ * 384];       // qkv -> ffn hidden (reused)

__device__ __forceinline__ float gelu_t(float x) {
    float x3 = x * x * x;
    return 0.5f * x * (1.f + tanhf(0.7978845608028654f * (x + 0.044715f * x3)));
}

// ---------------- layernorm: one row (H=128) per block -----------------------
__global__ void __launch_bounds__(128) ln_kernel(
    const float* __restrict__ x, const float* __restrict__ g,
    const float* __restrict__ b, float* __restrict__ y)
{
    long r = blockIdx.x;
    int t = threadIdx.x;
    float v = x[r * 128 + t];
    float s = v, s2 = v * v;
#pragma unroll
    for (int o = 16; o; o >>= 1) {
        s  += __shfl_xor_sync(0xffffffffu, s,  o);
        s2 += __shfl_xor_sync(0xffffffffu, s2, o);
    }
    __shared__ float red[8];
    int w = t >> 5;
    if ((t & 31) == 0) { red[w] = s; red[4 + w] = s2; }
    __syncthreads();
    s  = red[0] + red[1] + red[2] + red[3];
    s2 = red[4] + red[5] + red[6] + red[7];
    float mean = s * (1.f / 128.f);
    float var  = s2 * (1.f / 128.f) - mean * mean;
    y[r * 128 + t] = (v - mean) * rsqrtf(var + 1e-5f) * g[t] + b[t];
}

// ---------------- generic tiled SGEMM --------------------------------------
// out[M, ncols] = epilogue( A@W (+ A2@W2) )
// epilogue: + bias[c] (+ rowvec[row/rowdiv][c]) -> gelu? -> + resid[row][c]
// A rows may be gathered via `gather` (row stride of A == its kdim).
#define BM 128
#define BN 128
#define BK 32
__global__ void __launch_bounds__(256) gemm_kernel(
    const float* __restrict__ A,  int kdA,
    const float* __restrict__ A2, int kdA2,
    const float* __restrict__ W,  const float* __restrict__ W2,
    const float* __restrict__ bias,
    const int*   __restrict__ gather,
    const float* __restrict__ rowvec, int rowdiv,
    const float* __restrict__ resid,
    float* __restrict__ out,
    int M, int ncols, int act)
{
    __shared__ float As[BK][BM];
    __shared__ float Ws[BK][BN];
    int tid  = threadIdx.x;
    int row0 = blockIdx.x * BM;
    int cb   = blockIdx.y * BN;
    int tx = tid & 15, ty = tid >> 4;

    float acc[8][8];
#pragma unroll
    for (int i = 0; i < 8; i++)
#pragma unroll
        for (int j = 0; j < 8; j++) acc[i][j] = 0.f;

    for (int pass = 0; pass < 2; pass++) {
        const float* Ap = pass ? A2 : A;
        const float* Wp = pass ? W2 : W;
        int kd = pass ? kdA2 : kdA;
        if (pass && !Ap) break;
        for (int k0 = 0; k0 < kd; k0 += BK) {
            // A tile -> As (transposed)
#pragma unroll
            for (int i = 0; i < 4; i++) {
                int lin = tid + i * 256;        // 0..1023 (float4 units)
                int r   = lin >> 3;
                int kf  = (lin & 7) * 4;
                float4 v = make_float4(0.f, 0.f, 0.f, 0.f);
                int gr = row0 + r;
                if (gr < M) {
                    long arow = gather ? (long)gather[gr] : (long)gr;
                    v = *(const float4*)(Ap + arow * kd + k0 + kf);
                }
                As[kf + 0][r] = v.x; As[kf + 1][r] = v.y;
                As[kf + 2][r] = v.z; As[kf + 3][r] = v.w;
            }
            // W tile -> Ws
#pragma unroll
            for (int i = 0; i < 4; i++) {
                int lin = tid + i * 256;
                int wr  = lin >> 5;             // 0..31
                int cf  = (lin & 31) * 4;
                float4 v = *(const float4*)(Wp + (long)(k0 + wr) * ncols + cb + cf);
                *(float4*)&Ws[wr][cf] = v;
            }
            __syncthreads();
#pragma unroll
            for (int kk = 0; kk < BK; kk++) {
                float a[8], w[8];
                *(float4*)&a[0] = *(const float4*)&As[kk][ty * 8];
                *(float4*)&a[4] = *(const float4*)&As[kk][ty * 8 + 4];
                *(float4*)&w[0] = *(const float4*)&Ws[kk][tx * 8];
                *(float4*)&w[4] = *(const float4*)&Ws[kk][tx * 8 + 4];
#pragma unroll
                for (int i = 0; i < 8; i++)
#pragma unroll
                    for (int j = 0; j < 8; j++) acc[i][j] += a[i] * w[j];
            }
            __syncthreads();
        }
    }
    // epilogue
#pragma unroll
    for (int i = 0; i < 8; i++) {
        int gr = row0 + ty * 8 + i;
        if (gr >= M) break;
        const float* rv = rowvec ? rowvec + (long)(gr / rowdiv) * 128 : nullptr;
#pragma unroll
        for (int j = 0; j < 8; j++) {
            int c = cb + tx * 8 + j;
            float v = acc[i][j];
            if (bias) v += bias[c];
            if (rv)   v += rv[c];
            if (act)  v = gelu_t(v);
            if (resid) v += resid[(long)gr * ncols + c];
            out[(long)gr * ncols + c] = v;
        }
    }
}

// ---------------- fused per-node attention ----------------------------------
// qkv[N*K,384] -> scores/softmax/ctx -> ctx@W_out+b -> edge residual + masked
// node aggregation + node residual.
#define ATTN_SMEM ((4 * 4096 + 16384 + 128) * 4)
__global__ void __launch_bounds__(256) attn_kernel(
    const float* __restrict__ qkv,
    const float* __restrict__ Wout, const float* __restrict__ bout,
    const int*   __restrict__ num_valid,
    const float* __restrict__ edge_feat, const float* __restrict__ node_feat,
    float* __restrict__ edge1, float* __restrict__ node1)
{
    extern __shared__ float sm[];
    float* sQ = sm;                 // [32][128]
    float* sK = sQ + 4096;
    float* sV = sK + 4096;
    float* sC = sV + 4096;
    float* sW = sC + 4096;          // [128][128]
    float* sNode = sW + 16384;      // [128]
    int n = blockIdx.x;
    int tid = threadIdx.x;

    const float* src = qkv + (long)n * 32 * 384;
#pragma unroll
    for (int i = 0; i < 12; i++) {
        int lin = tid + i * 256;    // float4 units, 0..3071
        int j = lin / 96, c4 = lin % 96;
        float4 v = *(const float4*)(src + j * 384 + c4 * 4);
        float* dst = (c4 < 32) ? &sQ[j * 128 + c4 * 4]
                   : (c4 < 64) ? &sK[j * 128 + (c4 - 32) * 4]
                               : &sV[j * 128 + (c4 - 64) * 4];
        *(float4*)dst = v;
    }
#pragma unroll
    for (int i = 0; i < 16; i++) {
        int lin = tid + i * 256;    // 0..4095 float4
        *(float4*)&sW[lin * 4] = *(const float4*)(Wout + lin * 4);
    }
    if (tid < 128) sNode[tid] = 0.f;
    __syncthreads();

    int nv = num_valid[n];
    {   // one (head, query) per thread: 8 heads x 32 queries = 256
        int head = tid >> 5, q = tid & 31;
        int hc = head * 16;
        float qv[16];
#pragma unroll
        for (int d = 0; d < 4; d++) *(float4*)&qv[d * 4] = *(const float4*)&sQ[q * 128 + hc + d * 4];
        float s[32];
#pragma unroll
        for (int j = 0; j < 32; j++) {
            float a = 0.f;
#pragma unroll
            for (int d = 0; d < 4; d++) {
                float4 kv = *(const float4*)&sK[j * 128 + hc + d * 4];
                a += qv[d*4]*kv.x + qv[d*4+1]*kv.y + qv[d*4+2]*kv.z + qv[d*4+3]*kv.w;
            }
            s[j] = a * 0.25f;       // 1/sqrt(16)
        }
        float m = -1e30f;
#pragma unroll
        for (int j = 0; j < 32; j++) if (j < nv && s[j] > m) m = s[j];
        float sum = 0.f;
#pragma unroll
        for (int j = 0; j < 32; j++) {
            float p = (j < nv) ? __expf(s[j] - m) : 0.f;
            s[j] = p; sum += p;
        }
        float inv = 1.f / sum;
        float ctx[16];
#pragma unroll
        for (int d = 0; d < 16; d++) ctx[d] = 0.f;
#pragma unroll
        for (int j = 0; j < 32; j++) {
            float p = s[j] * inv;
#pragma unroll
            for (int d = 0; d < 4; d++) {
                float4 vv = *(const float4*)&sV[j * 128 + hc + d * 4];
                ctx[d*4]   += p * vv.x; ctx[d*4+1] += p * vv.y;
                ctx[d*4+2] += p * vv.z; ctx[d*4+3] += p * vv.w;
            }
        }
#pragma unroll
        for (int d = 0; d < 4; d++) *(float4*)&sC[q * 128 + hc + d * 4] = *(float4*)&ctx[d * 4];
    }
    __syncthreads();

    {   // edge_out = ctx @ W_out + b; residual + masked node aggregation
        int q  = tid >> 3;
        int cb = (tid & 7) * 16;
        float acc[16];
#pragma unroll
        for (int i = 0; i < 16; i++) acc[i] = 0.f;
        for (int k = 0; k < 128; k += 4) {
            float4 a4 = *(const float4*)&sC[q * 128 + k];
            float av[4] = {a4.x, a4.y, a4.z, a4.w};
#pragma unroll
            for (int kk = 0; kk < 4; kk++) {
                float a = av[kk];
#pragma unroll
                for (int c4 = 0; c4 < 4; c4++) {
                    float4 w = *(const float4*)&sW[(k + kk) * 128 + cb + c4 * 4];
                    acc[c4*4]   += a * w.x; acc[c4*4+1] += a * w.y;
                    acc[c4*4+2] += a * w.z; acc[c4*4+3] += a * w.w;
                }
            }
        }
        long erow = ((long)n * 32 + q) * 128;
        bool valid = q < nv;
#pragma unroll
        for (int i = 0; i < 16; i++) {
            int c = cb + i;
            float e = acc[i] + bout[c];
            if (valid) atomicAdd(&sNode[c], e);
            edge1[erow + c] = e + edge_feat[erow + c];
        }
    }
    __syncthreads();
    if (tid < 128)
        node1[(long)n * 128 + tid] = sNode[tid] + node_feat[(long)n * 128 + tid];
}

// ---------------- driver -----------------------------------------------------
static void launch_gemm(const float* A, int kdA, const float* A2, int kdA2,
                        const float* W, const float* W2, const float* bias,
                        const int* gather, const float* rowvec, int rowdiv,
                        const float* resid, float* out, int M, int ncols, int act)
{
    dim3 g((M + BM - 1) / BM, ncols / BN);
    gemm_kernel<<<g, 256>>>(A, kdA, A2, kdA2, W, W2, bias, gather, rowvec, rowdiv,
                            resid, out, M, ncols, act);
}

extern "C" void kernel_launch(void* const* d_in, const int* in_sizes, int n_in,
                              void* d_out, int out_size)
{
    const float* node_features = (const float*)d_in[0];
    const float* edge_features = (const float*)d_in[1];
    const float* edge_attr     = (const float*)d_in[2];
    const int*   neighbor_list = (const int*)d_in[3];
    const int*   num_valid     = (const int*)d_in[4];
    const float* W_edge = (const float*)d_in[5];
    const float* b_edge = (const float*)d_in[6];
    const float* W_node = (const float*)d_in[7];
    const float* b_node = (const float*)d_in[8];
    const float* W_msg  = (const float*)d_in[9];
    const float* b_msg  = (const float*)d_in[10];
    const float* W_qkv  = (const float*)d_in[11];
    const float* b_qkv  = (const float*)d_in[12];
    const float* W_out  = (const float*)d_in[13];
    const float* b_out  = (const float*)d_in[14];
    const float* g_attn = (const float*)d_in[15];
    const float* be_attn= (const float*)d_in[16];
    const float* g_fn   = (const float*)d_in[17];
    const float* be_fn  = (const float*)d_in[18];
    const float* g_fe   = (const float*)d_in[19];
    const float* be_fe  = (const float*)d_in[20];
    const float* Wn1 = (const float*)d_in[21];
    const float* bn1 = (const float*)d_in[22];
    const float* Wn2 = (const float*)d_in[23];
    const float* bn2 = (const float*)d_in[24];
    const float* We1 = (const float*)d_in[25];
    const float* be1 = (const float*)d_in[26];
    const float* We2 = (const float*)d_in[27];
    const float* be2 = (const float*)d_in[28];

    float *s_nh, *s_c, *s_nf1, *s_eh, *s_nh2, *s_big;
    cudaGetSymbolAddress((void**)&s_nh,  S_nh);
    cudaGetSymbolAddress((void**)&s_c,   S_c);
    cudaGetSymbolAddress((void**)&s_nf1, S_nf1);
    cudaGetSymbolAddress((void**)&s_eh,  S_eh);
    cudaGetSymbolAddress((void**)&s_nh2, S_nh2);
    cudaGetSymbolAddress((void**)&s_big, S_big);

    float* out_node = (float*)d_out;
    float* out_edge = out_node + (long)N_ * H_;

    // 1) node_hidden = LN(node_features)
    ln_kernel<<<N_, 128>>>(node_features, g_attn, be_attn, s_nh);
    // 2) edge_hidden = gelu(edge_attr @ W_edge + b_edge)
    launch_gemm(edge_attr, 128, nullptr, 0, W_edge, nullptr, b_edge,
                nullptr, nullptr, 1, nullptr, s_eh, M_, 128, 1);
    // 3a) center proj: c = node_hidden @ W_node[:128]
    launch_gemm(s_nh, 128, nullptr, 0, W_node, nullptr, nullptr,
                nullptr, nullptr, 1, nullptr, s_c, N_, 128, 0);
    // 3b) node_hid = gelu(nbr @ W_node[128:] + c[n] + b_node)   (gathered rows)
    launch_gemm(s_nh, 128, nullptr, 0, W_node + 128 * 128, nullptr, b_node,
                neighbor_list, s_c, K_, nullptr, s_nh2, M_, 128, 1);
    // 4) msg = gelu(eh @ Wm_top + nh @ Wm_bot + b_msg)   (in-place over s_eh)
    launch_gemm(s_eh, 128, s_nh2, 128, W_msg, W_msg + 128 * 128, b_msg,
                nullptr, nullptr, 1, nullptr, s_eh, M_, 128, 1);
    // 5) qkv = msg @ W_qkv + b_qkv
    launch_gemm(s_eh, 128, nullptr, 0, W_qkv, nullptr, b_qkv,
                nullptr, nullptr, 1, nullptr, s_big, M_, 384, 0);
    // 6) attention + out proj + residuals + masked aggregation
    cudaFuncSetAttribute(attn_kernel, cudaFuncAttributeMaxDynamicSharedMemorySize, ATTN_SMEM);
    attn_kernel<<<N_, 256, ATTN_SMEM>>>(s_big, W_out, b_out, num_valid,
                                        edge_features, node_features,
                                        out_edge, s_nf1);
    // 7) node FFN
    ln_kernel<<<N_, 128>>>(s_nf1, g_fn, be_fn, s_c);
    launch_gemm(s_c, 128, nullptr, 0, Wn1, nullptr, bn1,
                nullptr, nullptr, 1, nullptr, s_big, N_, 256, 1);
    launch_gemm(s_big, 256, nullptr, 0, Wn2, nullptr, bn2,
                nullptr, nullptr, 1, s_nf1, out_node, N_, 128, 0);
    // 8) edge FFN (residual held in out_edge)
    ln_kernel<<<M_, 128>>>(out_edge, g_fe, be_fe, s_nh2);
    launch_gemm(s_nh2, 128, nullptr, 0, We1, nullptr, be1,
                nullptr, nullptr, 1, nullptr, s_big, M_, 256, 1);
    launch_gemm(s_big, 256, nullptr, 0, We2, nullptr, be2,
                nullptr, nullptr, 1, out_edge, out_edge, M_, 128, 0);
}

// round 2
// speedup vs baseline: 1.3302x; 1.3302x over previous
#include <cuda_runtime.h>
#include <cuda_bf16.h>
#include <cstdint>

// Problem constants
#define N_  10000
#define K_  32
#define M_  (N_ * K_)      // 320000
#define H_  128

// ---------------- scratch (device globals; no allocation allowed) -------------
__device__ float S_nh [N_ * H_];
__device__ float S_c  [N_ * H_];
__device__ float S_nf1[N_ * H_];
__device__ float S_eh [M_ * H_];
__device__ float S_nh2[M_ * H_];
__device__ float S_big[M_ * 384];

__device__ __forceinline__ float gelu_t(float x) {
    float x3 = x * x * x;
    return 0.5f * x * (1.f + tanhf(0.7978845608028654f * (x + 0.044715f * x3)));
}

__device__ __forceinline__ float4 tf32x4(float4 v) {
    asm("cvt.rna.tf32.f32 %0, %0;" : "+f"(v.x));
    asm("cvt.rna.tf32.f32 %0, %0;" : "+f"(v.y));
    asm("cvt.rna.tf32.f32 %0, %0;" : "+f"(v.z));
    asm("cvt.rna.tf32.f32 %0, %0;" : "+f"(v.w));
    return v;
}

// ---------------- layernorm -------------------------------------------------
__global__ void __launch_bounds__(128) ln_kernel(
    const float* __restrict__ x, const float* __restrict__ g,
    const float* __restrict__ b, float* __restrict__ y)
{
    long r = blockIdx.x;
    int t = threadIdx.x;
    float v = x[r * 128 + t];
    float s = v, s2 = v * v;
#pragma unroll
    for (int o = 16; o; o >>= 1) {
        s  += __shfl_xor_sync(0xffffffffu, s,  o);
        s2 += __shfl_xor_sync(0xffffffffu, s2, o);
    }
    __shared__ float red[8];
    int w = t >> 5;
    if ((t & 31) == 0) { red[w] = s; red[4 + w] = s2; }
    __syncthreads();
    s  = red[0] + red[1] + red[2] + red[3];
    s2 = red[4] + red[5] + red[6] + red[7];
    float mean = s * (1.f / 128.f);
    float var  = s2 * (1.f / 128.f) - mean * mean;
    y[r * 128 + t] = (v - mean) * rsqrtf(var + 1e-5f) * g[t] + b[t];
}

// ---------------- tf32 tensor-core GEMM --------------------------------------
// out[M, ncols] = epilogue( A@W (+ A2@W2) ), tf32 mma.sync, fp32 accumulate.
// epilogue: + bias[c] (+ rowvec[row/rowdiv][c]) -> gelu? -> + resid -> store
#define BM 128
#define BN 128
#define BK 32
__global__ void __launch_bounds__(256, 2) gemm_kernel(
    const float* __restrict__ A,  int kdA,
    const float* __restrict__ A2, int kdA2,
    const float* __restrict__ W,  const float* __restrict__ W2,
    const float* __restrict__ bias,
    const int*   __restrict__ gather,
    const float* __restrict__ rowvec, int rowdiv,
    const float* __restrict__ resid,
    float* __restrict__ out,
    int M, int ncols, int act)
{
    __shared__ float As[BM][36];     // [m][k], pad 36 -> frag reads conflict-free
    __shared__ float Ws[BK][136];    // [k][n], pad 136 -> frag reads conflict-free

    int tid  = threadIdx.x;
    int lane = tid & 31;
    int wid  = tid >> 5;
    int warp_m = wid >> 2;           // 0..1   (64 rows each)
    int warp_n = wid & 3;            // 0..3   (32 cols each)
    int qr = lane >> 2;              // 0..7
    int qc = lane & 3;               // 0..3
    int row0 = blockIdx.x * BM;
    int cb   = blockIdx.y * BN;

    float acc[4][4][4];
#pragma unroll
    for (int i = 0; i < 4; i++)
#pragma unroll
        for (int j = 0; j < 4; j++)
#pragma unroll
            for (int c = 0; c < 4; c++) acc[i][j][c] = 0.f;

    for (int pass = 0; pass < 2; pass++) {
        const float* Ap = pass ? A2 : A;
        const float* Wp = pass ? W2 : W;
        int kd = pass ? kdA2 : kdA;
        if (pass && !Ap) break;
        for (int k0 = 0; k0 < kd; k0 += BK) {
            // ---- A tile -> As[m][k] ----
#pragma unroll
            for (int i = 0; i < 4; i++) {
                int lin = tid + i * 256;         // 0..1023 float4 slots
                int r   = lin >> 3;
                int kf  = (lin & 7) * 4;
                float4 v = make_float4(0.f, 0.f, 0.f, 0.f);
                int gr = row0 + r;
                if (gr < M) {
                    long arow = gather ? (long)gather[gr] : (long)gr;
                    v = tf32x4(*(const float4*)(Ap + arow * kd + k0 + kf));
                }
                *(float4*)&As[r][kf] = v;
            }
            // ---- W tile -> Ws[k][n] ----
#pragma unroll
            for (int i = 0; i < 4; i++) {
                int lin = tid + i * 256;
                int wr  = lin >> 5;              // 0..31
                int cf  = (lin & 31) * 4;
                float4 v = tf32x4(*(const float4*)(Wp + (long)(k0 + wr) * ncols + cb + cf));
                *(float4*)&Ws[wr][cf] = v;
            }
            __syncthreads();

#pragma unroll
            for (int ks = 0; ks < 4; ks++) {
                int k8 = ks * 8;
                uint32_t af[4][4];
#pragma unroll
                for (int mt = 0; mt < 4; mt++) {
                    int mb = warp_m * 64 + mt * 16;
                    af[mt][0] = __float_as_uint(As[mb + qr    ][k8 + qc    ]);
                    af[mt][1] = __float_as_uint(As[mb + 8 + qr][k8 + qc    ]);
                    af[mt][2] = __float_as_uint(As[mb + qr    ][k8 + qc + 4]);
                    af[mt][3] = __float_as_uint(As[mb + 8 + qr][k8 + qc + 4]);
                }
                uint32_t bf[4][2];
#pragma unroll
                for (int nt = 0; nt < 4; nt++) {
                    int nb = warp_n * 32 + nt * 8;
                    bf[nt][0] = __float_as_uint(Ws[k8 + qc    ][nb + qr]);
                    bf[nt][1] = __float_as_uint(Ws[k8 + qc + 4][nb + qr]);
                }
#pragma unroll
                for (int mt = 0; mt < 4; mt++)
#pragma unroll
                    for (int nt = 0; nt < 4; nt++) {
                        asm volatile(
                            "mma.sync.aligned.m16n8k8.row.col.f32.tf32.tf32.f32 "
                            "{%0,%1,%2,%3}, {%4,%5,%6,%7}, {%8,%9}, {%0,%1,%2,%3};"
                            : "+f"(acc[mt][nt][0]), "+f"(acc[mt][nt][1]),
                              "+f"(acc[mt][nt][2]), "+f"(acc[mt][nt][3])
                            : "r"(af[mt][0]), "r"(af[mt][1]),
                              "r"(af[mt][2]), "r"(af[mt][3]),
                              "r"(bf[nt][0]), "r"(bf[nt][1]));
                    }
            }
            __syncthreads();
        }
    }

    // ---- epilogue: c0/c1 at (row, col..col+1), c2/c3 at (row+8, col..col+1)
#pragma unroll
    for (int mt = 0; mt < 4; mt++) {
#pragma unroll
        for (int half = 0; half < 2; half++) {
            int gr = row0 + warp_m * 64 + mt * 16 + half * 8 + qr;
            if (gr >= M) continue;
            const float* rv = rowvec ? rowvec + (long)(gr / rowdiv) * 128 : nullptr;
#pragma unroll
            for (int nt = 0; nt < 4; nt++) {
                int c = cb + warp_n * 32 + nt * 8 + qc * 2;
                float v0 = acc[mt][nt][half * 2 + 0];
                float v1 = acc[mt][nt][half * 2 + 1];
                if (bias) { v0 += bias[c];  v1 += bias[c + 1]; }
                if (rv)   { v0 += rv[c];    v1 += rv[c + 1]; }
                if (act)  { v0 = gelu_t(v0); v1 = gelu_t(v1); }
                long oidx = (long)gr * ncols + c;
                if (resid) {
                    float2 r2 = *(const float2*)(resid + oidx);
                    v0 += r2.x; v1 += r2.y;
                }
                *(float2*)(out + oidx) = make_float2(v0, v1);
            }
        }
    }
}

// ---------------- fused per-node attention ----------------------------------
#define ATTN_SMEM ((4 * 4096 + 16384 + 128) * 4)
__global__ void __launch_bounds__(256) attn_kernel(
    const float* __restrict__ qkv,
    const float* __restrict__ Wout, const float* __restrict__ bout,
    const int*   __restrict__ num_valid,
    const float* __restrict__ edge_feat, const float* __restrict__ node_feat,
    float* __restrict__ edge1, float* __restrict__ node1)
{
    extern __shared__ float sm[];
    float* sQ = sm;                 // [32][128]
    float* sK = sQ + 4096;
    float* sV = sK + 4096;
    float* sC = sV + 4096;
    float* sW = sC + 4096;          // [128][128]
    float* sNode = sW + 16384;      // [128]
    int n = blockIdx.x;
    int tid = threadIdx.x;

    const float* src = qkv + (long)n * 32 * 384;
#pragma unroll
    for (int i = 0; i < 12; i++) {
        int lin = tid + i * 256;    // float4 units, 0..3071
        int j = lin / 96, c4 = lin % 96;
        float4 v = *(const float4*)(src + j * 384 + c4 * 4);
        float* dst = (c4 < 32) ? &sQ[j * 128 + c4 * 4]
                   : (c4 < 64) ? &sK[j * 128 + (c4 - 32) * 4]
                               : &sV[j * 128 + (c4 - 64) * 4];
        *(float4*)dst = v;
    }
#pragma unroll
    for (int i = 0; i < 16; i++) {
        int lin = tid + i * 256;
        *(float4*)&sW[lin * 4] = *(const float4*)(Wout + lin * 4);
    }
    if (tid < 128) sNode[tid] = 0.f;
    __syncthreads();

    int nv = num_valid[n];
    {   // one (head, query) per thread
        int head = tid >> 5, q = tid & 31;
        int hc = head * 16;
        float qv[16];
#pragma unroll
        for (int d = 0; d < 4; d++) *(float4*)&qv[d * 4] = *(const float4*)&sQ[q * 128 + hc + d * 4];
        float s[32];
#pragma unroll
        for (int j = 0; j < 32; j++) {
            float a = 0.f;
#pragma unroll
            for (int d = 0; d < 4; d++) {
                float4 kv = *(const float4*)&sK[j * 128 + hc + d * 4];
                a += qv[d*4]*kv.x + qv[d*4+1]*kv.y + qv[d*4+2]*kv.z + qv[d*4+3]*kv.w;
            }
            s[j] = a * 0.25f;
        }
        float m = -1e30f;
#pragma unroll
        for (int j = 0; j < 32; j++) if (j < nv && s[j] > m) m = s[j];
        float sum = 0.f;
#pragma unroll
        for (int j = 0; j < 32; j++) {
            float p = (j < nv) ? __expf(s[j] - m) : 0.f;
            s[j] = p; sum += p;
        }
        float inv = 1.f / sum;
        float ctx[16];
#pragma unroll
        for (int d = 0; d < 16; d++) ctx[d] = 0.f;
#pragma unroll
        for (int j = 0; j < 32; j++) {
            float p = s[j] * inv;
#pragma unroll
            for (int d = 0; d < 4; d++) {
                float4 vv = *(const float4*)&sV[j * 128 + hc + d * 4];
                ctx[d*4]   += p * vv.x; ctx[d*4+1] += p * vv.y;
                ctx[d*4+2] += p * vv.z; ctx[d*4+3] += p * vv.w;
            }
        }
#pragma unroll
        for (int d = 0; d < 4; d++) *(float4*)&sC[q * 128 + hc + d * 4] = *(float4*)&ctx[d * 4];
    }
    __syncthreads();

    {   // edge_out = ctx @ W_out + b; residual + masked node aggregation
        int q  = tid >> 3;
        int cb2 = (tid & 7) * 16;
        float acc[16];
#pragma unroll
        for (int i = 0; i < 16; i++) acc[i] = 0.f;
        for (int k = 0; k < 128; k += 4) {
            float4 a4 = *(const float4*)&sC[q * 128 + k];
            float av[4] = {a4.x, a4.y, a4.z, a4.w};
#pragma unroll
            for (int kk = 0; kk < 4; kk++) {
                float a = av[kk];
#pragma unroll
                for (int c4 = 0; c4 < 4; c4++) {
                    float4 w = *(const float4*)&sW[(k + kk) * 128 + cb2 + c4 * 4];
                    acc[c4*4]   += a * w.x; acc[c4*4+1] += a * w.y;
                    acc[c4*4+2] += a * w.z; acc[c4*4+3] += a * w.w;
                }
            }
        }
        long erow = ((long)n * 32 + q) * 128;
        bool valid = q < nv;
#pragma unroll
        for (int i = 0; i < 16; i++) {
            int c = cb2 + i;
            float e = acc[i] + bout[c];
            if (valid) atomicAdd(&sNode[c], e);
            edge1[erow + c] = e + edge_feat[erow + c];
        }
    }
    __syncthreads();
    if (tid < 128)
        node1[(long)n * 128 + tid] = sNode[tid] + node_feat[(long)n * 128 + tid];
}

// ---------------- driver -----------------------------------------------------
static void launch_gemm(const float* A, int kdA, const float* A2, int kdA2,
                        const float* W, const float* W2, const float* bias,
                        const int* gather, const float* rowvec, int rowdiv,
                        const float* resid, float* out, int M, int ncols, int act)
{
    dim3 g((M + BM - 1) / BM, ncols / BN);
    gemm_kernel<<<g, 256>>>(A, kdA, A2, kdA2, W, W2, bias, gather, rowvec, rowdiv,
                            resid, out, M, ncols, act);
}

extern "C" void kernel_launch(void* const* d_in, const int* in_sizes, int n_in,
                              void* d_out, int out_size)
{
    const float* node_features = (const float*)d_in[0];
    const float* edge_features = (const float*)d_in[1];
    const float* edge_attr     = (const float*)d_in[2];
    const int*   neighbor_list = (const int*)d_in[3];
    const int*   num_valid     = (const int*)d_in[4];
    const float* W_edge = (const float*)d_in[5];
    const float* b_edge = (const float*)d_in[6];
    const float* W_node = (const float*)d_in[7];
    const float* b_node = (const float*)d_in[8];
    const float* W_msg  = (const float*)d_in[9];
    const float* b_msg  = (const float*)d_in[10];
    const float* W_qkv  = (const float*)d_in[11];
    const float* b_qkv  = (const float*)d_in[12];
    const float* W_out  = (const float*)d_in[13];
    const float* b_out  = (const float*)d_in[14];
    const float* g_attn = (const float*)d_in[15];
    const float* be_attn= (const float*)d_in[16];
    const float* g_fn   = (const float*)d_in[17];
    const float* be_fn  = (const float*)d_in[18];
    const float* g_fe   = (const float*)d_in[19];
    const float* be_fe  = (const float*)d_in[20];
    const float* Wn1 = (const float*)d_in[21];
    const float* bn1 = (const float*)d_in[22];
    const float* Wn2 = (const float*)d_in[23];
    const float* bn2 = (const float*)d_in[24];
    const float* We1 = (const float*)d_in[25];
    const float* be1 = (const float*)d_in[26];
    const float* We2 = (const float*)d_in[27];
    const float* be2 = (const float*)d_in[28];

    float *s_nh, *s_c, *s_nf1, *s_eh, *s_nh2, *s_big;
    cudaGetSymbolAddress((void**)&s_nh,  S_nh);
    cudaGetSymbolAddress((void**)&s_c,   S_c);
    cudaGetSymbolAddress((void**)&s_nf1, S_nf1);
    cudaGetSymbolAddress((void**)&s_eh,  S_eh);
    cudaGetSymbolAddress((void**)&s_nh2, S_nh2);
    cudaGetSymbolAddress((void**)&s_big, S_big);

    float* out_node = (float*)d_out;
    float* out_edge = out_node + (long)N_ * H_;

    // 1) node_hidden = LN(node_features)
    ln_kernel<<<N_, 128>>>(node_features, g_attn, be_attn, s_nh);
    // 2) edge_hidden = gelu(edge_attr @ W_edge + b_edge)
    launch_gemm(edge_attr, 128, nullptr, 0, W_edge, nullptr, b_edge,
                nullptr, nullptr, 1, nullptr, s_eh, M_, 128, 1);
    // 3a) center proj: c = node_hidden @ W_node[:128]
    launch_gemm(s_nh, 128, nullptr, 0, W_node, nullptr, nullptr,
                nullptr, nullptr, 1, nullptr, s_c, N_, 128, 0);
    // 3b) node_hid = gelu(nbr @ W_node[128:] + c[n] + b_node)
    launch_gemm(s_nh, 128, nullptr, 0, W_node + 128 * 128, nullptr, b_node,
                neighbor_list, s_c, K_, nullptr, s_nh2, M_, 128, 1);
    // 4) msg = gelu(eh @ Wm_top + nh @ Wm_bot + b_msg)
    launch_gemm(s_eh, 128, s_nh2, 128, W_msg, W_msg + 128 * 128, b_msg,
                nullptr, nullptr, 1, nullptr, s_eh, M_, 128, 1);
    // 5) qkv = msg @ W_qkv + b_qkv
    launch_gemm(s_eh, 128, nullptr, 0, W_qkv, nullptr, b_qkv,
                nullptr, nullptr, 1, nullptr, s_big, M_, 384, 0);
    // 6) attention + out proj + residuals + masked aggregation
    cudaFuncSetAttribute(attn_kernel, cudaFuncAttributeMaxDynamicSharedMemorySize, ATTN_SMEM);
    attn_kernel<<<N_, 256, ATTN_SMEM>>>(s_big, W_out, b_out, num_valid,
                                        edge_features, node_features,
                                        out_edge, s_nf1);
    // 7) node FFN
    ln_kernel<<<N_, 128>>>(s_nf1, g_fn, be_fn, s_c);
    launch_gemm(s_c, 128, nullptr, 0, Wn1, nullptr, bn1,
                nullptr, nullptr, 1, nullptr, s_big, N_, 256, 1);
    launch_gemm(s_big, 256, nullptr, 0, Wn2, nullptr, bn2,
                nullptr, nullptr, 1, s_nf1, out_node, N_, 128, 0);
    // 8) edge FFN
    ln_kernel<<<M_, 128>>>(out_edge, g_fe, be_fe, s_nh2);
    launch_gemm(s_nh2, 128, nullptr, 0, We1, nullptr, be1,
                nullptr, nullptr, 1, nullptr, s_big, M_, 256, 1);
    launch_gemm(s_big, 256, nullptr, 0, We2, nullptr, be2,
                nullptr, nullptr, 1, out_edge, out_edge, M_, 128, 0);
}

// round 3
// speedup vs baseline: 3.6650x; 2.7553x over previous
#include <cuda_runtime.h>
#include <cuda_bf16.h>
#include <cstdint>

// Problem constants
#define N_  10000
#define K_  32
#define M_  (N_ * K_)      // 320000
#define H_  128

// ---------------- scratch (device globals; no allocation allowed) -------------
__device__ float S_nh [N_ * H_];
__device__ float S_c  [N_ * H_];
__device__ float S_nf1[N_ * H_];
__device__ float S_eh [M_ * H_];
__device__ float S_nh2[M_ * H_];
__device__ float S_big[M_ * 384];
__device__ float S_w  [278528];          // rounded weights

__device__ __forceinline__ float gelu_t(float x) {
    float x3 = x * x * x;
    return 0.5f * x * (1.f + tanhf(0.7978845608028654f * (x + 0.044715f * x3)));
}
__device__ __forceinline__ float rtf(float x) {
    asm("cvt.rna.tf32.f32 %0, %0;" : "+f"(x));
    return x;
}

// ---------------- round-copy (tf32) ------------------------------------------
__global__ void __launch_bounds__(256) round_kernel(
    const float* __restrict__ src, float* __restrict__ dst, long n4)
{
    long i = (long)blockIdx.x * 256 + threadIdx.x;
    if (i >= n4) return;
    float4 v = ((const float4*)src)[i];
    v.x = rtf(v.x); v.y = rtf(v.y); v.z = rtf(v.z); v.w = rtf(v.w);
    ((float4*)dst)[i] = v;
}

// ---------------- layernorm ---------------------------------------------------
__global__ void __launch_bounds__(128) ln_kernel(
    const float* __restrict__ x, const float* __restrict__ g,
    const float* __restrict__ b, float* __restrict__ y, int rnd)
{
    long r = blockIdx.x;
    int t = threadIdx.x;
    float v = x[r * 128 + t];
    float s = v, s2 = v * v;
#pragma unroll
    for (int o = 16; o; o >>= 1) {
        s  += __shfl_xor_sync(0xffffffffu, s,  o);
        s2 += __shfl_xor_sync(0xffffffffu, s2, o);
    }
    __shared__ float red[8];
    int w = t >> 5;
    if ((t & 31) == 0) { red[w] = s; red[4 + w] = s2; }
    __syncthreads();
    s  = red[0] + red[1] + red[2] + red[3];
    s2 = red[4] + red[5] + red[6] + red[7];
    float mean = s * (1.f / 128.f);
    float var  = s2 * (1.f / 128.f) - mean * mean;
    float o = (v - mean) * rsqrtf(var + 1e-5f) * g[t] + b[t];
    y[r * 128 + t] = rnd ? rtf(o) : o;
}

// ---------------- pipelined tf32 tensor GEMM ----------------------------------
// out = epilogue( A@W (+ A2@W2) ); all GEMM inputs must be pre-rounded to tf32.
// flags: bit0 = gelu, bit1 = round output to tf32. out2 (optional): pre-residual.
#define BM 128
#define BN 128
#define BK 32
#define GEMM_SMEM 71680    // 2*(128*36 + 32*136)*4 bytes

__device__ __forceinline__ void cp16(uint32_t dst, const void* src, int sz) {
    asm volatile("cp.async.cg.shared.global [%0], [%1], 16, %2;"
                 :: "r"(dst), "l"(src), "r"(sz));
}

__global__ void __launch_bounds__(256, 2) gemm_kernel(
    const float* __restrict__ A,  int kdA,
    const float* __restrict__ A2, int kdA2,
    const float* __restrict__ W,  const float* __restrict__ W2,
    const float* __restrict__ bias,
    const int*   __restrict__ gather,
    const float* __restrict__ rowvec, int rowdiv,
    const float* __restrict__ resid,
    float* __restrict__ out, float* __restrict__ out2,
    int M, int ncols, int flags)
{
    extern __shared__ float sm[];
    // layout (floats): As0[128*36], As1[128*36], Ws0[32*136], Ws1[32*136]
    const int AS_STRIDE = 4608, WS_BASE = 9216, WS_STRIDE = 4352;

    int tid  = threadIdx.x;
    int lane = tid & 31;
    int wid  = tid >> 5;
    int warp_m = wid >> 2;
    int warp_n = wid & 3;
    int qr = lane >> 2;
    int qc = lane & 3;
    int row0 = blockIdx.x * BM;
    int cb   = blockIdx.y * BN;

    // ---- per-thread loader constants (hoisted) ----
    int kf  = (tid & 7) * 4;          // A: k-offset within tile
    int ar0 = tid >> 3;               // A: first row (rows ar0 + 32*i)
    int cf  = (tid & 31) * 4;         // W: col offset
    int wr0 = tid >> 5;               // W: first k-row (wr0 + 8*i)
    long arow_[4]; int pr_[4];
#pragma unroll
    for (int i = 0; i < 4; i++) {
        int gr = row0 + ar0 + 32 * i;
        pr_[i] = (gr < M) ? 16 : 0;
        arow_[i] = (gr < M) ? (gather ? (long)gather[gr] : (long)gr) : 0;
    }
    uint32_t smb = (uint32_t)__cvta_generic_to_shared(sm);
    uint32_t aDst = smb + (uint32_t)(ar0 * 36 + kf) * 4;
    uint32_t wDst = smb + (uint32_t)(WS_BASE + wr0 * 136 + cf) * 4;

    int t1 = kdA / BK;
    int nt = t1 + (A2 ? kdA2 / BK : 0);

    // ---- tile issue ----
#define ISSUE(T) do {                                                          \
        int _t = (T);                                                          \
        int _p = (_t >= t1);                                                   \
        const float* _Ap = _p ? A2 : A;                                        \
        const float* _Wp = _p ? W2 : W;                                        \
        int _kd = _p ? kdA2 : kdA;                                             \
        int _k0 = (_p ? _t - t1 : _t) * BK;                                    \
        int _s  = _t & 1;                                                      \
        uint32_t _ad = aDst + _s * (AS_STRIDE * 4);                            \
        uint32_t _wd = wDst + _s * (WS_STRIDE * 4);                            \
        _Pragma("unroll")                                                      \
        for (int _i = 0; _i < 4; _i++)                                         \
            cp16(_ad + _i * (32 * 36 * 4),                                     \
                 _Ap + arow_[_i] * _kd + _k0 + kf, pr_[_i]);                   \
        _Pragma("unroll")                                                      \
        for (int _i = 0; _i < 4; _i++)                                         \
            cp16(_wd + _i * (8 * 136 * 4),                                     \
                 _Wp + (long)(_k0 + wr0 + 8 * _i) * ncols + cb + cf, 16);      \
        asm volatile("cp.async.commit_group;" ::: "memory");                   \
    } while (0)

    float acc[4][4][4];
#pragma unroll
    for (int i = 0; i < 4; i++)
#pragma unroll
        for (int j = 0; j < 4; j++)
#pragma unroll
            for (int c = 0; c < 4; c++) acc[i][j][c] = 0.f;

    ISSUE(0);
    for (int t = 0; t < nt; t++) {
        int cur = t & 1;
        if (t + 1 < nt) {
            ISSUE(t + 1);
            asm volatile("cp.async.wait_group 1;" ::: "memory");
        } else {
            asm volatile("cp.async.wait_group 0;" ::: "memory");
        }
        __syncthreads();

        const float* Asf = sm + cur * AS_STRIDE + (warp_m * 64) * 36;
        const float* Wsf = sm + WS_BASE + cur * WS_STRIDE + warp_n * 32;
#pragma unroll
        for (int ks = 0; ks < 4; ks++) {
            int k8 = ks * 8;
            uint32_t af[4][4];
#pragma unroll
            for (int mt = 0; mt < 4; mt++) {
                const float* p = Asf + (mt * 16 + qr) * 36 + k8 + qc;
                af[mt][0] = __float_as_uint(p[0]);
                af[mt][1] = __float_as_uint(p[8 * 36]);
                af[mt][2] = __float_as_uint(p[4]);
                af[mt][3] = __float_as_uint(p[8 * 36 + 4]);
            }
            uint32_t bf[4][2];
#pragma unroll
            for (int nt2 = 0; nt2 < 4; nt2++) {
                const float* p = Wsf + (k8 + qc) * 136 + nt2 * 8 + qr;
                bf[nt2][0] = __float_as_uint(p[0]);
                bf[nt2][1] = __float_as_uint(p[4 * 136]);
            }
#pragma unroll
            for (int mt = 0; mt < 4; mt++)
#pragma unroll
                for (int nt2 = 0; nt2 < 4; nt2++) {
                    asm volatile(
                        "mma.sync.aligned.m16n8k8.row.col.f32.tf32.tf32.f32 "
                        "{%0,%1,%2,%3}, {%4,%5,%6,%7}, {%8,%9}, {%0,%1,%2,%3};"
                        : "+f"(acc[mt][nt2][0]), "+f"(acc[mt][nt2][1]),
                          "+f"(acc[mt][nt2][2]), "+f"(acc[mt][nt2][3])
                        : "r"(af[mt][0]), "r"(af[mt][1]),
                          "r"(af[mt][2]), "r"(af[mt][3]),
                          "r"(bf[nt2][0]), "r"(bf[nt2][1]));
                }
        }
        __syncthreads();
    }
#undef ISSUE

    int gelu = flags & 1, rnd = flags & 2;
#pragma unroll
    for (int mt = 0; mt < 4; mt++) {
#pragma unroll
        for (int half = 0; half < 2; half++) {
            int gr = row0 + warp_m * 64 + mt * 16 + half * 8 + qr;
            if (gr >= M) continue;
            const float* rv = rowvec ? rowvec + (long)(gr / rowdiv) * 128 : nullptr;
#pragma unroll
            for (int nt2 = 0; nt2 < 4; nt2++) {
                int c = cb + warp_n * 32 + nt2 * 8 + qc * 2;
                float v0 = acc[mt][nt2][half * 2 + 0];
                float v1 = acc[mt][nt2][half * 2 + 1];
                if (bias) { v0 += bias[c];  v1 += bias[c + 1]; }
                if (rv)   { v0 += rv[c];    v1 += rv[c + 1]; }
                if (gelu) { v0 = gelu_t(v0); v1 = gelu_t(v1); }
                if (rnd)  { v0 = rtf(v0);    v1 = rtf(v1); }
                long oidx = (long)gr * ncols + c;
                if (out2) *(float2*)(out2 + oidx) = make_float2(v0, v1);
                if (resid) {
                    float2 r2 = *(const float2*)(resid + oidx);
                    v0 += r2.x; v1 += r2.y;
                }
                *(float2*)(out + oidx) = make_float2(v0, v1);
            }
        }
    }
}

// ---------------- attention core: QK^T / softmax / ctx only -------------------
#define ATTN_SMEM (4 * 4096 * 4)
__global__ void __launch_bounds__(256) attn_kernel(
    const float* __restrict__ qkv,
    const int*   __restrict__ num_valid,
    float* __restrict__ ctx_out)
{
    extern __shared__ float sm[];
    float* sQ = sm;
    float* sK = sQ + 4096;
    float* sV = sK + 4096;
    float* sC = sV + 4096;
    int n = blockIdx.x;
    int tid = threadIdx.x;

    const float* src = qkv + (long)n * 32 * 384;
#pragma unroll
    for (int i = 0; i < 12; i++) {
        int lin = tid + i * 256;
        int j = lin / 96, c4 = lin % 96;
        float4 v = *(const float4*)(src + j * 384 + c4 * 4);
        float* dst = (c4 < 32) ? &sQ[j * 128 + c4 * 4]
                   : (c4 < 64) ? &sK[j * 128 + (c4 - 32) * 4]
                               : &sV[j * 128 + (c4 - 64) * 4];
        *(float4*)dst = v;
    }
    __syncthreads();

    int nv = num_valid[n];
    {
        int head = tid >> 5, q = tid & 31;
        int hc = head * 16;
        float qv[16];
#pragma unroll
        for (int d = 0; d < 4; d++)
            *(float4*)&qv[d * 4] = *(const float4*)&sQ[q * 128 + hc + d * 4];
        float s[32];
#pragma unroll
        for (int j = 0; j < 32; j++) {
            float a = 0.f;
#pragma unroll
            for (int d = 0; d < 4; d++) {
                float4 kv = *(const float4*)&sK[j * 128 + hc + d * 4];
                a += qv[d*4]*kv.x + qv[d*4+1]*kv.y + qv[d*4+2]*kv.z + qv[d*4+3]*kv.w;
            }
            s[j] = a * 0.25f;
        }
        float m = -1e30f;
#pragma unroll
        for (int j = 0; j < 32; j++) if (j < nv && s[j] > m) m = s[j];
        float sum = 0.f;
#pragma unroll
        for (int j = 0; j < 32; j++) {
            float p = (j < nv) ? __expf(s[j] - m) : 0.f;
            s[j] = p; sum += p;
        }
        float inv = 1.f / sum;
        float ctx[16];
#pragma unroll
        for (int d = 0; d < 16; d++) ctx[d] = 0.f;
#pragma unroll
        for (int j = 0; j < 32; j++) {
            float p = s[j] * inv;
#pragma unroll
            for (int d = 0; d < 4; d++) {
                float4 vv = *(const float4*)&sV[j * 128 + hc + d * 4];
                ctx[d*4]   += p * vv.x; ctx[d*4+1] += p * vv.y;
                ctx[d*4+2] += p * vv.z; ctx[d*4+3] += p * vv.w;
            }
        }
#pragma unroll
        for (int d = 0; d < 16; d++) ctx[d] = rtf(ctx[d]);   // tf32 for outproj GEMM
#pragma unroll
        for (int d = 0; d < 4; d++)
            *(float4*)&sC[q * 128 + hc + d * 4] = *(float4*)&ctx[d * 4];
    }
    __syncthreads();

    float* dst = ctx_out + (long)n * 32 * 128;
#pragma unroll
    for (int i = 0; i < 4; i++) {
        int lin = tid + i * 256;
        *(float4*)(dst + lin * 4) = *(const float4*)&sC[lin * 4];
    }
}

// ---------------- masked scatter-aggregate ------------------------------------
__global__ void __launch_bounds__(128) agg_kernel(
    const float* __restrict__ edge_out, const float* __restrict__ node_feat,
    const int* __restrict__ num_valid, float* __restrict__ node1)
{
    int n = blockIdx.x, t = threadIdx.x;
    int nv = num_valid[n];
    const float* p = edge_out + (long)n * 32 * 128 + t;
    float s = 0.f;
    for (int k = 0; k < nv; k++) s += p[k * 128];
    node1[(long)n * 128 + t] = s + node_feat[(long)n * 128 + t];
}

// ---------------- driver -------------------------------------------------------
static void launch_gemm(const float* A, int kdA, const float* A2, int kdA2,
                        const float* W, const float* W2, const float* bias,
                        const int* gather, const float* rowvec, int rowdiv,
                        const float* resid, float* out, float* out2,
                        int M, int ncols, int flags)
{
    dim3 g((M + BM - 1) / BM, ncols / BN);
    gemm_kernel<<<g, 256, GEMM_SMEM>>>(A, kdA, A2, kdA2, W, W2, bias, gather,
                                       rowvec, rowdiv, resid, out, out2,
                                       M, ncols, flags);
}
static void launch_round(const float* src, float* dst, long n) {
    long n4 = n / 4;
    round_kernel<<<(unsigned)((n4 + 255) / 256), 256>>>(src, dst, n4);
}

extern "C" void kernel_launch(void* const* d_in, const int* in_sizes, int n_in,
                              void* d_out, int out_size)
{
    const float* node_features = (const float*)d_in[0];
    const float* edge_features = (const float*)d_in[1];
    const float* edge_attr     = (const float*)d_in[2];
    const int*   neighbor_list = (const int*)d_in[3];
    const int*   num_valid     = (const int*)d_in[4];
    const float* W_edge = (const float*)d_in[5];
    const float* b_edge = (const float*)d_in[6];
    const float* W_node = (const float*)d_in[7];
    const float* b_node = (const float*)d_in[8];
    const float* W_msg  = (const float*)d_in[9];
    const float* b_msg  = (const float*)d_in[10];
    const float* W_qkv  = (const float*)d_in[11];
    const float* b_qkv  = (const float*)d_in[12];
    const float* W_out  = (const float*)d_in[13];
    const float* b_out  = (const float*)d_in[14];
    const float* g_attn = (const float*)d_in[15];
    const float* be_attn= (const float*)d_in[16];
    const float* g_fn   = (const float*)d_in[17];
    const float* be_fn  = (const float*)d_in[18];
    const float* g_fe   = (const float*)d_in[19];
    const float* be_fe  = (const float*)d_in[20];
    const float* Wn1 = (const float*)d_in[21];
    const float* bn1 = (const float*)d_in[22];
    const float* Wn2 = (const float*)d_in[23];
    const float* bn2 = (const float*)d_in[24];
    const float* We1 = (const float*)d_in[25];
    const float* be1 = (const float*)d_in[26];
    const float* We2 = (const float*)d_in[27];
    const float* be2 = (const float*)d_in[28];

    float *s_nh, *s_c, *s_nf1, *s_eh, *s_nh2, *s_big, *s_w;
    cudaGetSymbolAddress((void**)&s_nh,  S_nh);
    cudaGetSymbolAddress((void**)&s_c,   S_c);
    cudaGetSymbolAddress((void**)&s_nf1, S_nf1);
    cudaGetSymbolAddress((void**)&s_eh,  S_eh);
    cudaGetSymbolAddress((void**)&s_nh2, S_nh2);
    cudaGetSymbolAddress((void**)&s_big, S_big);
    cudaGetSymbolAddress((void**)&s_w,   S_w);

    cudaFuncSetAttribute(gemm_kernel, cudaFuncAttributeMaxDynamicSharedMemorySize, GEMM_SMEM);
    cudaFuncSetAttribute(attn_kernel, cudaFuncAttributeMaxDynamicSharedMemorySize, ATTN_SMEM);

    float* out_node = (float*)d_out;
    float* out_edge = out_node + (long)N_ * H_;

    // rounded-weight scratch offsets
    float* rW_edge = s_w;              // 16384
    float* rW_node = s_w + 16384;      // 32768
    float* rW_msg  = s_w + 49152;      // 32768
    float* rW_qkv  = s_w + 81920;      // 49152
    float* rW_out  = s_w + 131072;     // 16384
    float* rWn1    = s_w + 147456;     // 32768
    float* rWn2    = s_w + 180224;     // 32768
    float* rWe1    = s_w + 212992;     // 32768
    float* rWe2    = s_w + 245760;     // 32768

    // 0) pre-round weights + edge_attr to tf32
    launch_round(W_edge, rW_edge, 16384);
    launch_round(W_node, rW_node, 32768);
    launch_round(W_msg,  rW_msg,  32768);
    launch_round(W_qkv,  rW_qkv,  49152);
    launch_round(W_out,  rW_out,  16384);
    launch_round(Wn1,    rWn1,    32768);
    launch_round(Wn2,    rWn2,    32768);
    launch_round(We1,    rWe1,    32768);
    launch_round(We2,    rWe2,    32768);
    launch_round(edge_attr, s_big, (long)M_ * 128);

    // 1) node_hidden = LN(node_features)  (rounded)
    ln_kernel<<<N_, 128>>>(node_features, g_attn, be_attn, s_nh, 1);
    // 2) edge_hidden = gelu(edge_attr @ W_edge + b)  (rounded)
    launch_gemm(s_big, 128, nullptr, 0, rW_edge, nullptr, b_edge,
                nullptr, nullptr, 1, nullptr, s_eh, nullptr, M_, 128, 3);
    // 3a) center proj (f32, epilogue-only consumer)
    launch_gemm(s_nh, 128, nullptr, 0, rW_node, nullptr, nullptr,
                nullptr, nullptr, 1, nullptr, s_c, nullptr, N_, 128, 0);
    // 3b) node_hid = gelu(nbr@Wnode_bot + center + b)  (rounded)
    launch_gemm(s_nh, 128, nullptr, 0, rW_node + 128 * 128, nullptr, b_node,
                neighbor_list, s_c, K_, nullptr, s_nh2, nullptr, M_, 128, 3);
    // 4) msg = gelu(eh@Wm_top + nh@Wm_bot + b)  (rounded, in-place)
    launch_gemm(s_eh, 128, s_nh2, 128, rW_msg, rW_msg + 128 * 128, b_msg,
                nullptr, nullptr, 1, nullptr, s_eh, nullptr, M_, 128, 3);
    // 5) qkv = msg @ W_qkv + b  (full f32 out for attention)
    launch_gemm(s_eh, 128, nullptr, 0, rW_qkv, nullptr, b_qkv,
                nullptr, nullptr, 1, nullptr, s_big, nullptr, M_, 384, 0);
    // 6a) attention core -> ctx (tf32-rounded) into s_nh2
    attn_kernel<<<N_, 256, ATTN_SMEM>>>(s_big, num_valid, s_nh2);
    // 6b) out-projection: edge_out=s_eh (pre-resid), out_edge=+edge_features
    launch_gemm(s_nh2, 128, nullptr, 0, rW_out, nullptr, b_out,
                nullptr, nullptr, 1, edge_features, out_edge, s_eh, M_, 128, 0);
    // 6c) masked aggregation + node residual
    agg_kernel<<<N_, 128>>>(s_eh, node_features, num_valid, s_nf1);
    // 7) node FFN
    ln_kernel<<<N_, 128>>>(s_nf1, g_fn, be_fn, s_c, 1);
    launch_gemm(s_c, 128, nullptr, 0, rWn1, nullptr, bn1,
                nullptr, nullptr, 1, nullptr, s_big, nullptr, N_, 256, 3);
    launch_gemm(s_big, 256, nullptr, 0, rWn2, nullptr, bn2,
                nullptr, nullptr, 1, s_nf1, out_node, nullptr, N_, 128, 0);
    // 8) edge FFN
    ln_kernel<<<M_, 128>>>(out_edge, g_fe, be_fe, s_nh2, 1);
    launch_gemm(s_nh2, 128, nullptr, 0, rWe1, nullptr, be1,
                nullptr, nullptr, 1, nullptr, s_big, nullptr, M_, 256, 3);
    launch_gemm(s_big, 256, nullptr, 0, rWe2, nullptr, be2,
                nullptr, nullptr, 1, out_edge, out_edge, nullptr, M_, 128, 0);
}

// round 5
// speedup vs baseline: 4.4164x; 1.2050x over previous
#include <cuda_runtime.h>
#include <cuda_fp16.h>
#include <cstdint>

// Problem constants
#define N_  10000
#define K_  32
#define M_  (N_ * K_)      // 320000
#define H_  128

// ---------------- scratch (device globals; no allocation allowed) -------------
__device__ float S_nh [N_ * H_];        // used as half: LN outputs
__device__ float S_c  [N_ * H_];        // f32 center proj / half FFN-LN
__device__ float S_nf1[N_ * H_];
__device__ float S_eh [M_ * H_];        // half edge_hidden/msg ; f32 pre-resid edge_out
__device__ float S_nh2[M_ * H_];        // half node_hid / ctx / edge-FFN LN
__device__ float S_big[M_ * 384];       // half edge_attr ; f32 qkv ; half ffn hidden
__device__ float S_w  [139264];         // transposed half weights (as halves: 278528)

__device__ __forceinline__ float gelu_t(float x) {
    float x3 = x * x * x;
    return 0.5f * x * (1.f + tanhf(0.7978845608028654f * (x + 0.044715f * x3)));
}

// ---------------- f32 -> f16 copy ----------------------------------------------
__global__ void __launch_bounds__(256) half_kernel(
    const float* __restrict__ src, __half* __restrict__ dst, long n4)
{
    long i = (long)blockIdx.x * 256 + threadIdx.x;
    if (i >= n4) return;
    float4 v = ((const float4*)src)[i];
    ((__half2*)dst)[i * 2 + 0] = __floats2half2_rn(v.x, v.y);
    ((__half2*)dst)[i * 2 + 1] = __floats2half2_rn(v.z, v.w);
}

// ---------------- transpose + halve: src[K][N] -> dst[N][K] ----------------------
__global__ void __launch_bounds__(256) transpose_half(
    const float* __restrict__ src, __half* __restrict__ dst, int Krows, int Ncols)
{
    __shared__ float tile[32][33];
    int bx = blockIdx.x * 32, by = blockIdx.y * 32;
    int x = threadIdx.x & 31, y4 = threadIdx.x >> 5;
#pragma unroll
    for (int j = 0; j < 4; j++) {
        int r = by + y4 + j * 8;
        if (r < Krows && bx + x < Ncols)
            tile[y4 + j * 8][x] = src[(long)r * Ncols + bx + x];
    }
    __syncthreads();
#pragma unroll
    for (int j = 0; j < 4; j++) {
        int n = bx + y4 + j * 8;
        if (n < Ncols && by + x < Krows)
            dst[(long)n * Krows + by + x] = __float2half_rn(tile[x][y4 + j * 8]);
    }
}

// ---------------- layernorm (mode: 0 = f32 out, 1 = f16 out) ---------------------
__global__ void __launch_bounds__(128) ln_kernel(
    const float* __restrict__ x, const float* __restrict__ g,
    const float* __restrict__ b, void* __restrict__ y, int mode)
{
    long r = blockIdx.x;
    int t = threadIdx.x;
    float v = x[r * 128 + t];
    float s = v, s2 = v * v;
#pragma unroll
    for (int o = 16; o; o >>= 1) {
        s  += __shfl_xor_sync(0xffffffffu, s,  o);
        s2 += __shfl_xor_sync(0xffffffffu, s2, o);
    }
    __shared__ float red[8];
    int w = t >> 5;
    if ((t & 31) == 0) { red[w] = s; red[4 + w] = s2; }
    __syncthreads();
    s  = red[0] + red[1] + red[2] + red[3];
    s2 = red[4] + red[5] + red[6] + red[7];
    float mean = s * (1.f / 128.f);
    float var  = s2 * (1.f / 128.f) - mean * mean;
    float o = (v - mean) * rsqrtf(var + 1e-5f) * g[t] + b[t];
    if (mode) ((__half*)y)[r * 128 + t] = __float2half_rn(o);
    else      ((float*)y)[r * 128 + t] = o;
}

// ---------------- pipelined fp16 tensor GEMM -------------------------------------
// out = epilogue( A@Wt^T (+ A2@Wt2^T) ); A [M,kd] f16 (opt. gathered rows),
// Wt [ncols, kd] f16 (K-major). flags: bit0 gelu, bit1 f16 output.
// out2 (f32, optional): pre-residual copy (f32 path only).
#define BK 32
#define AS_BYTES 10240          // 128 rows * 40 halves * 2
#define WS_OFF   20480
#define GEMM_SMEM 40960

__device__ __forceinline__ void cp16(uint32_t dst, const void* src, int sz) {
    asm volatile("cp.async.cg.shared.global [%0], [%1], 16, %2;"
                 :: "r"(dst), "l"(src), "r"(sz));
}

__global__ void __launch_bounds__(256, 2) gemm_h(
    const __half* __restrict__ A,  int kdA,
    const __half* __restrict__ A2, int kdA2,
    const __half* __restrict__ Wt, const __half* __restrict__ Wt2,
    const float* __restrict__ bias,
    const int*   __restrict__ gather,
    const float* __restrict__ rowvec, int rowdiv,
    const float* __restrict__ resid,
    void* __restrict__ out, float* __restrict__ out2,
    int M, int ncols, int flags)
{
    extern __shared__ __half smh[];
    uint32_t smb = (uint32_t)__cvta_generic_to_shared(smh);

    int tid  = threadIdx.x;
    int lane = tid & 31;
    int wid  = tid >> 5;
    int warp_m = wid >> 2;           // 0..1
    int warp_n = wid & 3;            // 0..3
    int qr = lane >> 2;              // group id 0..7
    int qc = lane & 3;               // thread-in-group
    int row0 = blockIdx.x * 128;
    int cb   = blockIdx.y * 128;

    // loader: 512 16B-chunks per operand, 2 per thread
    int kc = tid & 3;                // 16B chunk within 32-half row
    int lrow0 = tid >> 2;            // rows lrow0, lrow0+64
    long arow_[2]; int pr_[2];
#pragma unroll
    for (int i = 0; i < 2; i++) {
        int gr = row0 + lrow0 + 64 * i;
        pr_[i] = (gr < M) ? 16 : 0;
        arow_[i] = (gr < M) ? (gather ? (long)gather[gr] : (long)gr) : 0;
    }
    int t1 = kdA / BK;
    int nt = t1 + (A2 ? kdA2 / BK : 0);

#define ISSUE(T) do {                                                           \
        int _t = (T); int _p = (_t >= t1);                                      \
        const __half* _Ap = _p ? A2 : A;                                        \
        const __half* _Wp = _p ? Wt2 : Wt;                                      \
        int _kd = _p ? kdA2 : kdA;                                              \
        int _k0 = (_p ? _t - t1 : _t) * BK;                                     \
        uint32_t _ab = smb + (_t & 1) * AS_BYTES;                               \
        uint32_t _wb = smb + WS_OFF + (_t & 1) * AS_BYTES;                      \
        _Pragma("unroll")                                                       \
        for (int _i = 0; _i < 2; _i++)                                          \
            cp16(_ab + (lrow0 + 64 * _i) * 80 + kc * 16,                        \
                 _Ap + arow_[_i] * _kd + _k0 + kc * 8, pr_[_i]);                \
        _Pragma("unroll")                                                       \
        for (int _i = 0; _i < 2; _i++)                                          \
            cp16(_wb + (lrow0 + 64 * _i) * 80 + kc * 16,                        \
                 _Wp + (long)(cb + lrow0 + 64 * _i) * _kd + _k0 + kc * 8, 16);  \
        asm volatile("cp.async.commit_group;" ::: "memory");                    \
    } while (0)

    float acc[4][4][4];
#pragma unroll
    for (int i = 0; i < 4; i++)
#pragma unroll
        for (int j = 0; j < 4; j++)
#pragma unroll
            for (int c = 0; c < 4; c++) acc[i][j][c] = 0.f;

    ISSUE(0);
    for (int t = 0; t < nt; t++) {
        int cur = t & 1;
        if (t + 1 < nt) {
            ISSUE(t + 1);
            asm volatile("cp.async.wait_group 1;" ::: "memory");
        } else {
            asm volatile("cp.async.wait_group 0;" ::: "memory");
        }
        __syncthreads();

        const __half* Asf = smh + cur * (AS_BYTES / 2) + (warp_m * 64) * 40;
        const __half* Wsf = smh + (WS_OFF / 2) + cur * (AS_BYTES / 2) + (warp_n * 32) * 40;
#pragma unroll
        for (int ks = 0; ks < 2; ks++) {
            int k16 = ks * 16;
            uint32_t af[4][4];
#pragma unroll
            for (int mt = 0; mt < 4; mt++) {
                const __half* p = Asf + (mt * 16 + qr) * 40 + k16 + qc * 2;
                af[mt][0] = *(const uint32_t*)(p);
                af[mt][1] = *(const uint32_t*)(p + 8 * 40);
                af[mt][2] = *(const uint32_t*)(p + 8);
                af[mt][3] = *(const uint32_t*)(p + 8 * 40 + 8);
            }
            uint32_t bf[4][2];
#pragma unroll
            for (int nt2 = 0; nt2 < 4; nt2++) {
                const __half* p = Wsf + (nt2 * 8 + qr) * 40 + k16 + qc * 2;
                bf[nt2][0] = *(const uint32_t*)(p);
                bf[nt2][1] = *(const uint32_t*)(p + 8);
            }
#pragma unroll
            for (int mt = 0; mt < 4; mt++)
#pragma unroll
                for (int nt2 = 0; nt2 < 4; nt2++) {
                    asm volatile(
                        "mma.sync.aligned.m16n8k16.row.col.f32.f16.f16.f32 "
                        "{%0,%1,%2,%3}, {%4,%5,%6,%7}, {%8,%9}, {%0,%1,%2,%3};"
                        : "+f"(acc[mt][nt2][0]), "+f"(acc[mt][nt2][1]),
                          "+f"(acc[mt][nt2][2]), "+f"(acc[mt][nt2][3])
                        : "r"(af[mt][0]), "r"(af[mt][1]),
                          "r"(af[mt][2]), "r"(af[mt][3]),
                          "r"(bf[nt2][0]), "r"(bf[nt2][1]));
                }
        }
        __syncthreads();
    }
#undef ISSUE

    int gelu = flags & 1, halfout = flags & 2;
#pragma unroll
    for (int mt = 0; mt < 4; mt++) {
#pragma unroll
        for (int hh = 0; hh < 2; hh++) {
            int gr = row0 + warp_m * 64 + mt * 16 + hh * 8 + qr;
            if (gr >= M) continue;
            const float* rv = rowvec ? rowvec + (long)(gr / rowdiv) * 128 : nullptr;
#pragma unroll
            for (int nt2 = 0; nt2 < 4; nt2++) {
                int c = cb + warp_n * 32 + nt2 * 8 + qc * 2;
                float v0 = acc[mt][nt2][hh * 2 + 0];
                float v1 = acc[mt][nt2][hh * 2 + 1];
                if (bias) { v0 += bias[c];  v1 += bias[c + 1]; }
                if (rv)   { v0 += rv[c];    v1 += rv[c + 1]; }
                if (gelu) { v0 = gelu_t(v0); v1 = gelu_t(v1); }
                long oidx = (long)gr * ncols + c;
                if (halfout) {
                    *(__half2*)((__half*)out + oidx) = __floats2half2_rn(v0, v1);
                } else {
                    if (out2) *(float2*)(out2 + oidx) = make_float2(v0, v1);
                    if (resid) {
                        float2 r2 = *(const float2*)(resid + oidx);
                        v0 += r2.x; v1 += r2.y;
                    }
                    *(float2*)((float*)out + oidx) = make_float2(v0, v1);
                }
            }
        }
    }
}

// ---------------- attention core: QK^T / softmax / ctx (f16 out) -----------------
#define ATTN_SMEM (4 * 4096 * 4)
__global__ void __launch_bounds__(256) attn_kernel(
    const float* __restrict__ qkv,
    const int*   __restrict__ num_valid,
    __half* __restrict__ ctx_out)
{
    extern __shared__ float sm[];
    float* sQ = sm;
    float* sK = sQ + 4096;
    float* sV = sK + 4096;
    float* sC = sV + 4096;
    int n = blockIdx.x;
    int tid = threadIdx.x;

    const float* src = qkv + (long)n * 32 * 384;
#pragma unroll
    for (int i = 0; i < 12; i++) {
        int lin = tid + i * 256;
        int j = lin / 96, c4 = lin % 96;
        float4 v = *(const float4*)(src + j * 384 + c4 * 4);
        float* dst = (c4 < 32) ? &sQ[j * 128 + c4 * 4]
                   : (c4 < 64) ? &sK[j * 128 + (c4 - 32) * 4]
                               : &sV[j * 128 + (c4 - 64) * 4];
        *(float4*)dst = v;
    }
    __syncthreads();

    int nv = num_valid[n];
    {
        int head = tid >> 5, q = tid & 31;
        int hc = head * 16;
        float qv[16];
#pragma unroll
        for (int d = 0; d < 4; d++)
            *(float4*)&qv[d * 4] = *(const float4*)&sQ[q * 128 + hc + d * 4];
        float s[32];
#pragma unroll
        for (int j = 0; j < 32; j++) {
            float a = 0.f;
#pragma unroll
            for (int d = 0; d < 4; d++) {
                float4 kv = *(const float4*)&sK[j * 128 + hc + d * 4];
                a += qv[d*4]*kv.x + qv[d*4+1]*kv.y + qv[d*4+2]*kv.z + qv[d*4+3]*kv.w;
            }
            s[j] = a * 0.25f;
        }
        float m = -1e30f;
#pragma unroll
        for (int j = 0; j < 32; j++) if (j < nv && s[j] > m) m = s[j];
        float sum = 0.f;
#pragma unroll
        for (int j = 0; j < 32; j++) {
            float p = (j < nv) ? __expf(s[j] - m) : 0.f;
            s[j] = p; sum += p;
        }
        float inv = 1.f / sum;
        float ctx[16];
#pragma unroll
        for (int d = 0; d < 16; d++) ctx[d] = 0.f;
#pragma unroll
        for (int j = 0; j < 32; j++) {
            float p = s[j] * inv;
#pragma unroll
            for (int d = 0; d < 4; d++) {
                float4 vv = *(const float4*)&sV[j * 128 + hc + d * 4];
                ctx[d*4]   += p * vv.x; ctx[d*4+1] += p * vv.y;
                ctx[d*4+2] += p * vv.z; ctx[d*4+3] += p * vv.w;
            }
        }
#pragma unroll
        for (int d = 0; d < 4; d++)
            *(float4*)&sC[q * 128 + hc + d * 4] = *(float4*)&ctx[d * 4];
    }
    __syncthreads();

    __half* dst = ctx_out + (long)n * 32 * 128;
#pragma unroll
    for (int i = 0; i < 4; i++) {
        int lin = tid + i * 256;
        float4 v = *(const float4*)&sC[lin * 4];
        *(__half2*)(dst + lin * 4)     = __floats2half2_rn(v.x, v.y);
        *(__half2*)(dst + lin * 4 + 2) = __floats2half2_rn(v.z, v.w);
    }
}

// ---------------- masked scatter-aggregate ---------------------------------------
__global__ void __launch_bounds__(128) agg_kernel(
    const float* __restrict__ edge_out, const float* __restrict__ node_feat,
    const int* __restrict__ num_valid, float* __restrict__ node1)
{
    int n = blockIdx.x, t = threadIdx.x;
    int nv = num_valid[n];
    const float* p = edge_out + (long)n * 32 * 128 + t;
    float s = 0.f;
    for (int k = 0; k < nv; k++) s += p[k * 128];
    node1[(long)n * 128 + t] = s + node_feat[(long)n * 128 + t];
}

// ---------------- driver -----------------------------------------------------------
static void launch_gemm(const __half* A, int kdA, const __half* A2, int kdA2,
                        const __half* Wt, const __half* Wt2, const float* bias,
                        const int* gather, const float* rowvec, int rowdiv,
                        const float* resid, void* out, float* out2,
                        int M, int ncols, int flags)
{
    dim3 g((M + 127) / 128, ncols / 128);
    gemm_h<<<g, 256, GEMM_SMEM>>>(A, kdA, A2, kdA2, Wt, Wt2, bias, gather,
                                  rowvec, rowdiv, resid, out, out2,
                                  M, ncols, flags);
}
static void launch_T(const float* src, __half* dst, int K, int N) {
    dim3 g((N + 31) / 32, (K + 31) / 32);
    transpose_half<<<g, 256>>>(src, dst, K, N);
}
static void launch_half(const float* src, __half* dst, long n) {
    long n4 = n / 4;
    half_kernel<<<(unsigned)((n4 + 255) / 256), 256>>>(src, dst, n4);
}

extern "C" void kernel_launch(void* const* d_in, const int* in_sizes, int n_in,
                              void* d_out, int out_size)
{
    const float* node_features = (const float*)d_in[0];
    const float* edge_features = (const float*)d_in[1];
    const float* edge_attr     = (const float*)d_in[2];
    const int*   neighbor_list = (const int*)d_in[3];
    const int*   num_valid     = (const int*)d_in[4];
    const float* W_edge = (const float*)d_in[5];
    const float* b_edge = (const float*)d_in[6];
    const float* W_node = (const float*)d_in[7];
    const float* b_node = (const float*)d_in[8];
    const float* W_msg  = (const float*)d_in[9];
    const float* b_msg  = (const float*)d_in[10];
    const float* W_qkv  = (const float*)d_in[11];
    const float* b_qkv  = (const float*)d_in[12];
    const float* W_out  = (const float*)d_in[13];
    const float* b_out  = (const float*)d_in[14];
    const float* g_attn = (const float*)d_in[15];
    const float* be_attn= (const float*)d_in[16];
    const float* g_fn   = (const float*)d_in[17];
    const float* be_fn  = (const float*)d_in[18];
    const float* g_fe   = (const float*)d_in[19];
    const float* be_fe  = (const float*)d_in[20];
    const float* Wn1 = (const float*)d_in[21];
    const float* bn1 = (const float*)d_in[22];
    const float* Wn2 = (const float*)d_in[23];
    const float* bn2 = (const float*)d_in[24];
    const float* We1 = (const float*)d_in[25];
    const float* be1 = (const float*)d_in[26];
    const float* We2 = (const float*)d_in[27];
    const float* be2 = (const float*)d_in[28];

    float *s_nh, *s_c, *s_nf1, *s_eh, *s_nh2, *s_big, *s_w;
    cudaGetSymbolAddress((void**)&s_nh,  S_nh);
    cudaGetSymbolAddress((void**)&s_c,   S_c);
    cudaGetSymbolAddress((void**)&s_nf1, S_nf1);
    cudaGetSymbolAddress((void**)&s_eh,  S_eh);
    cudaGetSymbolAddress((void**)&s_nh2, S_nh2);
    cudaGetSymbolAddress((void**)&s_big, S_big);
    cudaGetSymbolAddress((void**)&s_w,   S_w);

    cudaFuncSetAttribute(attn_kernel, cudaFuncAttributeMaxDynamicSharedMemorySize, ATTN_SMEM);

    float* out_node = (float*)d_out;
    float* out_edge = out_node + (long)N_ * H_;

    // half-typed views
    __half* h_nh  = (__half*)s_nh;       // LN(node)
    __half* h_ea  = (__half*)s_big;      // rounded edge_attr (consumed by step 2)
    __half* h_eh  = (__half*)s_eh;       // edge_hidden / msg
    __half* h_nh2 = (__half*)s_nh2;      // node_hid / ctx / edge-FFN LN
    __half* h_c   = (__half*)s_c;        // node-FFN LN
    __half* h_hid = (__half*)s_big;      // FFN hidden (after qkv consumed)
    float*  f_pre = s_eh;                // pre-resid edge_out (f32, after msg consumed)

    // transposed half weights in S_w (offsets in halves)
    __half* wbase = (__half*)s_w;
    __half* tW_edge  = wbase;            // [128][128]
    __half* tW_nodeC = wbase + 16384;
    __half* tW_nodeN = wbase + 32768;
    __half* tW_msgE  = wbase + 49152;
    __half* tW_msgN  = wbase + 65536;
    __half* tW_qkv   = wbase + 81920;    // [384][128]
    __half* tW_out   = wbase + 131072;
    __half* tWn1     = wbase + 147456;   // [256][128]
    __half* tWn2     = wbase + 180224;   // [128][256]
    __half* tWe1     = wbase + 212992;
    __half* tWe2     = wbase + 245760;

    // 0) transpose+halve weights; halve edge_attr
    launch_T(W_edge,            tW_edge,  128, 128);
    launch_T(W_node,            tW_nodeC, 128, 128);
    launch_T(W_node + 128*128,  tW_nodeN, 128, 128);
    launch_T(W_msg,             tW_msgE,  128, 128);
    launch_T(W_msg + 128*128,   tW_msgN,  128, 128);
    launch_T(W_qkv,             tW_qkv,   128, 384);
    launch_T(W_out,             tW_out,   128, 128);
    launch_T(Wn1,               tWn1,     128, 256);
    launch_T(Wn2,               tWn2,     256, 128);
    launch_T(We1,               tWe1,     128, 256);
    launch_T(We2,               tWe2,     256, 128);
    launch_half(edge_attr, h_ea, (long)M_ * 128);

    // 1) node_hidden = LN(node_features) -> f16
    ln_kernel<<<N_, 128>>>(node_features, g_attn, be_attn, h_nh, 1);
    // 2) edge_hidden = gelu(edge_attr @ W_edge + b) -> f16
    launch_gemm(h_ea, 128, nullptr, 0, tW_edge, nullptr, b_edge,
                nullptr, nullptr, 1, nullptr, h_eh, nullptr, M_, 128, 3);
    // 3a) center proj -> f32 (rowvec addend)
    launch_gemm(h_nh, 128, nullptr, 0, tW_nodeC, nullptr, nullptr,
                nullptr, nullptr, 1, nullptr, s_c, nullptr, N_, 128, 0);
    // 3b) node_hid = gelu(nbr@WnodeN + center + b) -> f16 (gathered)
    launch_gemm(h_nh, 128, nullptr, 0, tW_nodeN, nullptr, b_node,
                neighbor_list, s_c, K_, nullptr, h_nh2, nullptr, M_, 128, 3);
    // 4) msg = gelu(eh@WmE + nh@WmN + b) -> f16 (in-place)
    launch_gemm(h_eh, 128, h_nh2, 128, tW_msgE, tW_msgN, b_msg,
                nullptr, nullptr, 1, nullptr, h_eh, nullptr, M_, 128, 3);
    // 5) qkv = msg @ W_qkv + b -> f32 (overwrites h_ea region, already consumed)
    launch_gemm(h_eh, 128, nullptr, 0, tW_qkv, nullptr, b_qkv,
                nullptr, nullptr, 1, nullptr, s_big, nullptr, M_, 384, 0);
    // 6a) attention core -> ctx f16 (overwrites node_hid)
    attn_kernel<<<N_, 256, ATTN_SMEM>>>(s_big, num_valid, h_nh2);
    // 6b) out-projection: out2 = f_pre (pre-resid), out = edge residual
    launch_gemm(h_nh2, 128, nullptr, 0, tW_out, nullptr, b_out,
                nullptr, nullptr, 1, edge_features, out_edge, f_pre, M_, 128, 0);
    // 6c) masked aggregation + node residual
    agg_kernel<<<N_, 128>>>(f_pre, node_features, num_valid, s_nf1);
    // 7) node FFN
    ln_kernel<<<N_, 128>>>(s_nf1, g_fn, be_fn, h_c, 1);
    launch_gemm(h_c, 128, nullptr, 0, tWn1, nullptr, bn1,
                nullptr, nullptr, 1, nullptr, h_hid, nullptr, N_, 256, 3);
    launch_gemm(h_hid, 256, nullptr, 0, tWn2, nullptr, bn2,
                nullptr, nullptr, 1, s_nf1, out_node, nullptr, N_, 128, 0);
    // 8) edge FFN
    ln_kernel<<<M_, 128>>>(out_edge, g_fe, be_fe, h_nh2, 1);
    launch_gemm(h_nh2, 128, nullptr, 0, tWe1, nullptr, be1,
                nullptr, nullptr, 1, nullptr, h_hid, nullptr, M_, 256, 3);
    launch_gemm(h_hid, 256, nullptr, 0, tWe2, nullptr, be2,
                nullptr, nullptr, 1, out_edge, out_edge, nullptr, M_, 128, 0);
}